// round 8
// baseline (speedup 1.0000x reference)
#include <cuda_runtime.h>
#include <cuda_bf16.h>
#include <math.h>
#include <stdint.h>

#define BB   4
#define NN   10000
#define EE   100000
#define CIN  16
#define NF   128
#define WN   384
#define OUTD 40
#define MROWS (BB*EE)            // 400000
#define ALPHA_C 0.25f
#define BN_EPS_C 1e-5f
#define M_TOT 40000.0f
#define KPAD 136                 // bf16 smem row stride (ldmatrix conflict-free)
#define TROW 3104                // T row stride in floats (3072 data + 24 bias + pad)
#define TDATA 3096               // used portion of a T row
#define GEMM1_SMEM (2*128*KPAD*2 + 2*128*KPAD*2)   // 139264
#define TB_NODES 16
#define TB_SMEM  (16*TROW*4 + TB_NODES*CIN*4)      // 198656 + 1024 = 199680
#define CE 20                    // edges per chunk in edge pass

// ---------------- device scratch (statics; no allocations) -------------------
__device__ float g_xnew[BB*NN*CIN];
__device__ float g_h[(size_t)MROWS*NF];            // 204.8 MB
__device__ float g_T[(size_t)BB*NN*TROW];          // 496.6 MB
__device__ float g_W2p[CIN*TROW];                  // rearranged W2 (+bias row)
__device__ float g_agg[BB*NN*OUTD];
__device__ float g_cnt[NN];
__device__ float g_sum[OUTD];
__device__ float g_sumsq[OUTD];
__device__ int   g_scnt[NN];
__device__ int   g_soff[NN+1];
__device__ int   g_spos[NN];
__device__ int   g_sedge[EE];
__device__ __align__(16) __nv_bfloat16 g_w1t_hi[NF*NF];   // [n][k]
__device__ __align__(16) __nv_bfloat16 g_w1t_lo[NF*NF];

// ---------------- zero scratch -----------------------------------------------
__global__ void zero_kernel() {
    int i = blockIdx.x * blockDim.x + threadIdx.x;
    if (i < BB*NN*OUTD) g_agg[i] = 0.0f;
    if (i < NN) { g_cnt[i] = 0.0f; g_scnt[i] = 0; }
    if (i < OUTD) { g_sum[i] = 0.0f; g_sumsq[i] = 0.0f; }
}

// ---------------- W1 transpose + bf16 hi/lo split ----------------------------
__global__ void prep1_kernel(const float* __restrict__ w1) {
    int idx = blockIdx.x * blockDim.x + threadIdx.x;
    if (idx < NF*NF) {
        int n = idx / NF, k = idx % NF;
        float v = w1[k*NF + n];
        __nv_bfloat16 hi = __float2bfloat16(v);
        g_w1t_hi[idx] = hi;
        g_w1t_lo[idx] = __float2bfloat16(v - __bfloat162float(hi));
    }
}

// ---------------- W2 rearrange: W2p[i][k*24+o] = w2[k][col(i,o)] -------------
// o<16: col=i*16+o ; o in 16..23: col=256+i*8+(o-16). Row j=3072+o holds b2[col].
__global__ void prep2_kernel(const float* __restrict__ w2,
                             const float* __restrict__ b2) {
    int idx = blockIdx.x * blockDim.x + threadIdx.x;
    if (idx >= CIN*TROW) return;
    int i = idx / TROW, j = idx % TROW;
    float v = 0.f;
    if (j < 3072) {
        int k = j / 24, o = j % 24;
        int col = (o < 16) ? (i*16 + o) : (256 + i*8 + (o - 16));
        v = w2[k*WN + col];
    } else if (j < TDATA) {
        int o = j - 3072;
        int col = (o < 16) ? (i*16 + o) : (256 + i*8 + (o - 16));
        v = b2[col];
    }
    g_W2p[i*TROW + j] = v;
}

// ---------------- closed-form FFT time mixing (proven) -----------------------
__global__ void xnew_kernel(const float* __restrict__ x,
                            const float* __restrict__ wr,
                            const float* __restrict__ wi) {
    __shared__ float sWr[CIN][CIN];
    __shared__ float sWi[CIN][CIN];
    int t = threadIdx.x;
    {
        int i = t >> 4, o = t & 15;
        sWr[i][o] = wr[i*32 + o*2 + 0] + wr[i*32 + o*2 + 1];
        sWi[i][o] = wi[i*32 + o*2 + 0] + wi[i*32 + o*2 + 1];
    }
    __syncthreads();
    int idx = blockIdx.x * blockDim.x + t;
    if (idx >= NN*CIN) return;
    int n = idx >> 4, o = idx & 15;
    float x0r = 0.f, re1 = 0.f, im1 = 0.f;
    #pragma unroll
    for (int i = 0; i < CIN; i++) {
        float a0 = x[(0*NN + n)*CIN + i];
        float a1 = x[(1*NN + n)*CIN + i];
        float a2 = x[(2*NN + n)*CIN + i];
        float a3 = x[(3*NN + n)*CIN + i];
        float S = a0 + a1 + a2 + a3;
        float P = a0 - a2;
        float Q = a3 - a1;
        float wrv = sWr[i][o], wiv = sWi[i][o];
        x0r += S * wrv;
        re1 += P * wrv - Q * wiv;
        im1 += P * wiv + Q * wrv;
    }
    g_xnew[(0*NN + n)*CIN + o] = 0.25f*(x0r + 2.f*re1);
    g_xnew[(1*NN + n)*CIN + o] = 0.25f*(x0r - 2.f*im1);
    g_xnew[(2*NN + n)*CIN + o] = 0.25f*(x0r - 2.f*re1);
    g_xnew[(3*NN + n)*CIN + o] = 0.25f*(x0r + 2.f*im1);
}

// ---------------- degree counts (dst for mean, src for sort) -----------------
__global__ void count_kernel(const int* __restrict__ eidx) {
    int e = blockIdx.x * blockDim.x + threadIdx.x;
    if (e < EE) {
        atomicAdd(&g_cnt[eidx[EE + e]], 1.0f);
        atomicAdd(&g_scnt[eidx[e]], 1);
    }
}

// ---------------- single-block exclusive scan over src counts ----------------
__global__ void scan_kernel() {
    __shared__ int part[256];
    int t = threadIdx.x;
    int n0 = t * 40;
    int n1 = min(n0 + 40, NN);
    int s = 0;
    for (int i = n0; i < n1; i++) s += g_scnt[i];
    part[t] = s;
    __syncthreads();
    for (int off = 1; off < 256; off <<= 1) {
        int v = 0;
        if (t >= off) v = part[t - off];
        __syncthreads();
        part[t] += v;
        __syncthreads();
    }
    int run = (t == 0) ? 0 : part[t - 1];
    for (int i = n0; i < n1; i++) {
        g_soff[i] = run;
        g_spos[i] = run;
        run += g_scnt[i];
    }
    if (t == 0) g_soff[NN] = EE;
}

__global__ void scatter_kernel(const int* __restrict__ eidx) {
    int e = blockIdx.x * blockDim.x + threadIdx.x;
    if (e < EE) {
        int p = atomicAdd(&g_spos[eidx[e]], 1);
        g_sedge[p] = e;
    }
}

// ---------------- mma.sync helpers (proven in R6) ----------------------------
__device__ __forceinline__ void mma_bf16(float* c, const unsigned* a, const unsigned* b) {
    asm volatile(
        "mma.sync.aligned.m16n8k16.row.col.f32.bf16.bf16.f32 "
        "{%0,%1,%2,%3}, {%4,%5,%6,%7}, {%8,%9}, {%0,%1,%2,%3};\n"
        : "+f"(c[0]), "+f"(c[1]), "+f"(c[2]), "+f"(c[3])
        : "r"(a[0]), "r"(a[1]), "r"(a[2]), "r"(a[3]), "r"(b[0]), "r"(b[1]));
}
__device__ __forceinline__ void ldmat4(unsigned* a, const __nv_bfloat16* p) {
    unsigned addr = (unsigned)__cvta_generic_to_shared(p);
    asm volatile("ldmatrix.sync.aligned.m8n8.x4.shared.b16 {%0,%1,%2,%3}, [%4];"
                 : "=r"(a[0]), "=r"(a[1]), "=r"(a[2]), "=r"(a[3]) : "r"(addr));
}

__device__ __forceinline__ void gemm_3term(
    const __nv_bfloat16* __restrict__ sAhi, const __nv_bfloat16* __restrict__ sAlo,
    const __nv_bfloat16* __restrict__ sWhi, const __nv_bfloat16* __restrict__ sWlo,
    int warp, int lane, float acc[8][2][4])
{
    #pragma unroll
    for (int term = 0; term < 3; term++) {
        const __nv_bfloat16* A = (term < 2) ? sAhi : sAlo;
        const __nv_bfloat16* W = (term == 1) ? sWlo : sWhi;
        const __nv_bfloat16* Arow = A + (lane & 15)*KPAD + (lane >> 4)*8;
        const __nv_bfloat16* Wb = W + (warp*16 + (lane >> 2))*KPAD + (lane & 3)*2;
        #pragma unroll
        for (int k0 = 0; k0 < 128; k0 += 16) {
            unsigned b0[2], b1[2];
            b0[0] = *(const unsigned*)&Wb[k0];
            b0[1] = *(const unsigned*)&Wb[k0 + 8];
            b1[0] = *(const unsigned*)&Wb[8*KPAD + k0];
            b1[1] = *(const unsigned*)&Wb[8*KPAD + k0 + 8];
            #pragma unroll
            for (int mt = 0; mt < 8; mt++) {
                unsigned a[4];
                ldmat4(a, Arow + mt*16*KPAD + k0);
                mma_bf16(acc[mt][0], a, b0);
                mma_bf16(acc[mt][1], a, b1);
            }
        }
    }
}

// ---------------- GEMM1: h = relu(ea@W1 + b1), f32 out -----------------------
__global__ __launch_bounds__(256, 1)
void gemm1_tc_kernel(const float* __restrict__ ea, const float* __restrict__ b1g)
{
    extern __shared__ char smem_raw[];
    __nv_bfloat16* sAhi = (__nv_bfloat16*)smem_raw;            // 128 x KPAD
    __nv_bfloat16* sAlo = sAhi + 128*KPAD;
    __nv_bfloat16* sWhi = sAlo + 128*KPAD;
    __nv_bfloat16* sWlo = sWhi + 128*KPAD;
    const int tid  = threadIdx.x;
    const int warp = tid >> 5, lane = tid & 31;
    const int row0 = blockIdx.x * 128;

    // load A tile (128x128 f32) and split into bf16 hi/lo
    #pragma unroll
    for (int t = 0; t < 16; t++) {
        int idx = tid + t * 256;
        int r = idx >> 5, q = (idx & 31) << 2;
        float4 v = *(const float4*)&ea[(size_t)(row0 + r)*NF + q];
        __nv_bfloat16 hx = __float2bfloat16(v.x);
        __nv_bfloat16 hy = __float2bfloat16(v.y);
        __nv_bfloat16 hz = __float2bfloat16(v.z);
        __nv_bfloat16 hw = __float2bfloat16(v.w);
        __nv_bfloat162* ph = (__nv_bfloat162*)&sAhi[r*KPAD + q];
        ph[0] = __nv_bfloat162(hx, hy);
        ph[1] = __nv_bfloat162(hz, hw);
        __nv_bfloat162* pl = (__nv_bfloat162*)&sAlo[r*KPAD + q];
        pl[0] = __nv_bfloat162(__float2bfloat16(v.x - __bfloat162float(hx)),
                               __float2bfloat16(v.y - __bfloat162float(hy)));
        pl[1] = __nv_bfloat162(__float2bfloat16(v.z - __bfloat162float(hz)),
                               __float2bfloat16(v.w - __bfloat162float(hw)));
    }
    // stage W1T hi/lo
    #pragma unroll
    for (int t = 0; t < 8; t++) {
        int idx = tid + t * 256;
        int n = idx >> 4, q = (idx & 15) << 3;
        *(float4*)&sWhi[n*KPAD + q] = *(const float4*)&g_w1t_hi[n*NF + q];
        *(float4*)&sWlo[n*KPAD + q] = *(const float4*)&g_w1t_lo[n*NF + q];
    }
    __syncthreads();

    float acc[8][2][4];
    #pragma unroll
    for (int mt = 0; mt < 8; mt++)
        #pragma unroll
        for (int nt = 0; nt < 2; nt++)
            #pragma unroll
            for (int q = 0; q < 4; q++) acc[mt][nt][q] = 0.f;

    gemm_3term(sAhi, sAlo, sWhi, sWlo, warp, lane, acc);

    // epilogue: bias + relu, f32 to g_h
    int c0 = warp*16 + (lane & 3)*2;
    int r0 = lane >> 2;
    #pragma unroll
    for (int nt = 0; nt < 2; nt++) {
        int col = c0 + nt*8;
        float bc0 = __ldg(&b1g[col]), bc1 = __ldg(&b1g[col + 1]);
        #pragma unroll
        for (int mt = 0; mt < 8; mt++) {
            #pragma unroll
            for (int half = 0; half < 2; half++) {
                size_t row = (size_t)(row0 + mt*16 + r0 + half*8);
                g_h[row*NF + col]     = fmaxf(acc[mt][nt][half*2 + 0] + bc0, 0.f);
                g_h[row*NF + col + 1] = fmaxf(acc[mt][nt][half*2 + 1] + bc1, 0.f);
            }
        }
    }
}

// ---------------- T build: T[bn][j] = sum_i xnew[bn][i] * W2p[i][j] ----------
__global__ __launch_bounds__(256, 1)
void tbuild_kernel() {
    extern __shared__ char smem_raw[];
    float* sW  = (float*)smem_raw;                 // 16 x TROW
    float* sxg = sW + CIN*TROW;                    // 16 nodes x 16
    const int tid = threadIdx.x;
    const int bn0 = blockIdx.x * TB_NODES;

    // stage W2p (coalesced f4)
    {
        const float4* src = (const float4*)g_W2p;
        float4* dst = (float4*)sW;
        for (int i = tid; i < CIN*TROW/4; i += 256) dst[i] = src[i];
    }
    if (tid < TB_NODES*CIN) {
        int node = tid >> 4, i = tid & 15;
        sxg[node*CIN + i] = g_xnew[(size_t)(bn0 + node)*CIN + i];
    }
    __syncthreads();

    #pragma unroll
    for (int g = 0; g < 4; g++) {
        float x[4][CIN];
        #pragma unroll
        for (int n4 = 0; n4 < 4; n4++)
            #pragma unroll
            for (int i = 0; i < CIN; i++)
                x[n4][i] = sxg[(g*4 + n4)*CIN + i];
        #pragma unroll
        for (int jt = 0; jt < 4; jt++) {
            int j4 = jt*256 + tid;
            if (j4 < TDATA/4 + (TDATA%4 ? 1 : 0)) {   // 3096/4 = 774
                int j = j4 * 4;
                float4 w4[CIN];
                #pragma unroll
                for (int i = 0; i < CIN; i++)
                    w4[i] = *(const float4*)&sW[i*TROW + j];
                #pragma unroll
                for (int n4 = 0; n4 < 4; n4++) {
                    float4 a = make_float4(0.f, 0.f, 0.f, 0.f);
                    #pragma unroll
                    for (int i = 0; i < CIN; i++) {
                        float xv = x[n4][i];
                        a.x += w4[i].x * xv;
                        a.y += w4[i].y * xv;
                        a.z += w4[i].z * xv;
                        a.w += w4[i].w * xv;
                    }
                    *(float4*)&g_T[(size_t)(bn0 + g*4 + n4)*TROW + j] = a;
                }
            }
        }
    }
}

// ---------------- edge pass: block per (b, src-node) -------------------------
__global__ __launch_bounds__(128)
void edge_kernel(const int* __restrict__ eidx, const float* __restrict__ esh) {
    __shared__ __align__(16) float sT[TROW];       // T row (12.4 KB)
    __shared__ float sH[CE*NF];                    // up to 20 h rows
    __shared__ int   sE[CE];
    __shared__ int   sDst[CE];
    __shared__ float4 sSh[CE];

    const int tid = threadIdx.x;
    const int bn = blockIdx.x;
    const int b  = bn / NN;
    const int n  = bn - b*NN;

    const int base = g_soff[n];
    const int nEdges = g_soff[n+1] - base;
    if (nEdges == 0) return;

    // load T row (f4, coalesced)
    {
        const float4* src = (const float4*)&g_T[(size_t)bn*TROW];
        float4* dst = (float4*)sT;
        for (int i = tid; i < TDATA/4 + 1; i += 128)
            if (i*4 < TROW) dst[i] = src[i];
    }

    for (int c0 = 0; c0 < nEdges; c0 += CE) {
        int ne = min(CE, nEdges - c0);
        __syncthreads();                    // prev chunk consumers done + T ready (1st)
        if (tid < ne) {
            int e = g_sedge[base + c0 + tid];
            sE[tid] = e;
            sDst[tid] = eidx[EE + e];
            sSh[tid] = *(const float4*)&esh[((size_t)b*EE + e)*4];
        }
        __syncthreads();
        for (int slot = 0; slot < ne; slot++)
            sH[slot*NF + tid] = g_h[((size_t)b*EE + sE[slot])*NF + tid];
        __syncthreads();

        int slot = tid / 6, og = tid - slot*6;     // 6 threads per edge, 4 o each
        if (slot < ne && tid < CE*6) {
            float4 acc = *(const float4*)&sT[3072 + og*4];   // bias term
            const float* hrow = &sH[slot*NF];
            #pragma unroll 4
            for (int k = 0; k < NF; k++) {
                float hv = hrow[k];
                float4 tv = *(const float4*)&sT[k*24 + og*4];
                acc.x += hv * tv.x;
                acc.y += hv * tv.y;
                acc.z += hv * tv.z;
                acc.w += hv * tv.w;
            }
            float4 sh = sSh[slot];
            float* aggp = &g_agg[((size_t)b*NN + sDst[slot])*OUTD];
            float av[4] = {acc.x, acc.y, acc.z, acc.w};
            #pragma unroll
            for (int j = 0; j < 4; j++) {
                int o = og*4 + j;
                if (o < 16) {
                    atomicAdd(&aggp[o], ALPHA_C * sh.x * av[j]);
                } else {
                    int c = o - 16;
                    float v = ALPHA_C * av[j];
                    atomicAdd(&aggp[16 + c*3 + 0], v * sh.y);
                    atomicAdd(&aggp[16 + c*3 + 1], v * sh.z);
                    atomicAdd(&aggp[16 + c*3 + 2], v * sh.w);
                }
            }
        }
    }
}

// ---------------- mean-by-count + BN stats (proven) --------------------------
__global__ void stats_kernel() {
    int row = blockIdx.x * blockDim.x + threadIdx.x;
    float v[OUTD];
    if (row < BB*NN) {
        int n = row % NN;
        float inv = 1.0f / fmaxf(g_cnt[n], 1.0f);
        float4* pp = (float4*)&g_agg[row*OUTD];
        #pragma unroll
        for (int t = 0; t < 10; t++) {
            float4 a = pp[t];
            a.x *= inv; a.y *= inv; a.z *= inv; a.w *= inv;
            pp[t] = a;
            v[t*4+0] = a.x; v[t*4+1] = a.y; v[t*4+2] = a.z; v[t*4+3] = a.w;
        }
    } else {
        #pragma unroll
        for (int c = 0; c < OUTD; c++) v[c] = 0.f;
    }
    #pragma unroll
    for (int c = 0; c < OUTD; c++) {
        float s = v[c], q = v[c]*v[c];
        #pragma unroll
        for (int off = 16; off > 0; off >>= 1) {
            s += __shfl_down_sync(0xffffffffu, s, off);
            q += __shfl_down_sync(0xffffffffu, q, off);
        }
        if ((threadIdx.x & 31) == 0) {
            atomicAdd(&g_sum[c],   s);
            atomicAdd(&g_sumsq[c], q);
        }
    }
}

__global__ void norm_kernel(float* __restrict__ out,
                            const float* __restrict__ gamma,
                            const float* __restrict__ beta) {
    int i = blockIdx.x * blockDim.x + threadIdx.x;
    if (i >= BB*NN*OUTD) return;
    int c = i % OUTD;
    const float invM = 1.0f / M_TOT;
    float mu  = g_sum[c] * invM;
    float var = g_sumsq[c] * invM - mu*mu;
    out[i] = (g_agg[i] - mu) * rsqrtf(var + BN_EPS_C) * gamma[c] + beta[c];
}

// ---------------- launch ------------------------------------------------------
extern "C" void kernel_launch(void* const* d_in, const int* in_sizes, int n_in,
                              void* d_out, int out_size) {
    const float* x     = (const float*)d_in[0];
    const int*   eidx  = (const int*)  d_in[1];
    const float* ea    = (const float*)d_in[2];
    const float* esh   = (const float*)d_in[3];
    const float* wr    = (const float*)d_in[4];
    const float* wi    = (const float*)d_in[5];
    const float* w1    = (const float*)d_in[6];
    const float* b1    = (const float*)d_in[7];
    const float* w2    = (const float*)d_in[8];
    const float* b2    = (const float*)d_in[9];
    const float* gamma = (const float*)d_in[10];
    const float* beta  = (const float*)d_in[11];
    float* out = (float*)d_out;

    cudaFuncSetAttribute(gemm1_tc_kernel,
                         cudaFuncAttributeMaxDynamicSharedMemorySize, GEMM1_SMEM);
    cudaFuncSetAttribute(tbuild_kernel,
                         cudaFuncAttributeMaxDynamicSharedMemorySize, TB_SMEM);

    zero_kernel   <<<(BB*NN*OUTD + 255)/256, 256>>>();
    xnew_kernel   <<<(NN*CIN + 255)/256, 256>>>(x, wr, wi);
    count_kernel  <<<(EE + 255)/256, 256>>>(eidx);
    scan_kernel   <<<1, 256>>>();
    scatter_kernel<<<(EE + 255)/256, 256>>>(eidx);
    prep1_kernel  <<<(NF*NF + 255)/256, 256>>>(w1);
    prep2_kernel  <<<(CIN*TROW + 255)/256, 256>>>(w2, b2);
    gemm1_tc_kernel<<<MROWS/128, 256, GEMM1_SMEM>>>(ea, b1);
    tbuild_kernel <<<BB*NN/TB_NODES, 256, TB_SMEM>>>();
    edge_kernel   <<<BB*NN, 128>>>(eidx, esh);
    stats_kernel  <<<(BB*NN + 255)/256, 256>>>();
    norm_kernel   <<<(BB*NN*OUTD + 255)/256, 256>>>(out, gamma, beta);
}

// round 9
// speedup vs baseline: 2.1800x; 2.1800x over previous
#include <cuda_runtime.h>
#include <cuda_fp16.h>
#include <math.h>

#define BB   4
#define NN   10000
#define EE   100000
#define CIN  16
#define NF   128
#define WN   384
#define OUTD 40
#define MROWS (BB*EE)            // 400000
#define ALPHA_C 0.25f
#define BN_EPS_C 1e-5f
#define M_TOT 40000.0f
#define KPAD 136                 // fp16 smem row stride (272B, ldmatrix conflict-free)
#define EWPAD 132                // f32 smem row stride for ew tile
#define OFF_A 0                  // 128*KPAD half = 34816 B
#define OFF_REG 34816            // union region: W chunk (34816) / sEw (67584)
#define SMEM_BYTES (34816 + 67584)   // 102400 -> 2 CTAs/SM

// ---------------- device scratch ---------------------------------------------
__device__ float g_xnew[BB*NN*CIN];
__device__ float g_agg[BB*NN*OUTD];
__device__ float g_cnt[NN];
__device__ float g_sum[OUTD];
__device__ float g_sumsq[OUTD];
__device__ __align__(16) __half g_w1t[NF*NF];   // [n][k] transposed fp16
__device__ __align__(16) __half g_w2t[WN*NF];   // [n][k] transposed fp16

// ---------------- zero scratch -----------------------------------------------
__global__ void zero_kernel() {
    int i = blockIdx.x * blockDim.x + threadIdx.x;
    if (i < BB*NN*OUTD) g_agg[i] = 0.0f;
    if (i < NN)         g_cnt[i] = 0.0f;
    if (i < OUTD) { g_sum[i] = 0.0f; g_sumsq[i] = 0.0f; }
}

// ---------------- weight transpose -> fp16 -----------------------------------
__global__ void prep_kernel(const float* __restrict__ w1,
                            const float* __restrict__ w2) {
    int idx = blockIdx.x * blockDim.x + threadIdx.x;
    if (idx < NF*NF) {
        int n = idx / NF, k = idx % NF;
        g_w1t[idx] = __float2half_rn(w1[k*NF + n]);
    }
    if (idx < WN*NF) {
        int n = idx / NF, k = idx % NF;
        g_w2t[idx] = __float2half_rn(w2[k*WN + n]);
    }
}

// ---------------- closed-form FFT time mixing (proven) -----------------------
__global__ void xnew_kernel(const float* __restrict__ x,
                            const float* __restrict__ wr,
                            const float* __restrict__ wi) {
    __shared__ float sWr[CIN][CIN];
    __shared__ float sWi[CIN][CIN];
    int t = threadIdx.x;
    {
        int i = t >> 4, o = t & 15;
        sWr[i][o] = wr[i*32 + o*2 + 0] + wr[i*32 + o*2 + 1];
        sWi[i][o] = wi[i*32 + o*2 + 0] + wi[i*32 + o*2 + 1];
    }
    __syncthreads();
    int idx = blockIdx.x * blockDim.x + t;
    if (idx >= NN*CIN) return;
    int n = idx >> 4, o = idx & 15;
    float x0r = 0.f, re1 = 0.f, im1 = 0.f;
    #pragma unroll
    for (int i = 0; i < CIN; i++) {
        float a0 = x[(0*NN + n)*CIN + i];
        float a1 = x[(1*NN + n)*CIN + i];
        float a2 = x[(2*NN + n)*CIN + i];
        float a3 = x[(3*NN + n)*CIN + i];
        float S = a0 + a1 + a2 + a3;
        float P = a0 - a2;
        float Q = a3 - a1;
        float wrv = sWr[i][o], wiv = sWi[i][o];
        x0r += S * wrv;
        re1 += P * wrv - Q * wiv;
        im1 += P * wiv + Q * wrv;
    }
    g_xnew[(0*NN + n)*CIN + o] = 0.25f*(x0r + 2.f*re1);
    g_xnew[(1*NN + n)*CIN + o] = 0.25f*(x0r - 2.f*im1);
    g_xnew[(2*NN + n)*CIN + o] = 0.25f*(x0r - 2.f*re1);
    g_xnew[(3*NN + n)*CIN + o] = 0.25f*(x0r + 2.f*im1);
}

// ---------------- per-node in-degree -----------------------------------------
__global__ void count_kernel(const int* __restrict__ eidx) {
    int e = blockIdx.x * blockDim.x + threadIdx.x;
    if (e < EE) atomicAdd(&g_cnt[eidx[EE + e]], 1.0f);
}

// ---------------- mma.sync fp16 helpers --------------------------------------
__device__ __forceinline__ void mma_f16(float* c, const unsigned* a, const unsigned* b) {
    asm volatile(
        "mma.sync.aligned.m16n8k16.row.col.f32.f16.f16.f32 "
        "{%0,%1,%2,%3}, {%4,%5,%6,%7}, {%8,%9}, {%0,%1,%2,%3};\n"
        : "+f"(c[0]), "+f"(c[1]), "+f"(c[2]), "+f"(c[3])
        : "r"(a[0]), "r"(a[1]), "r"(a[2]), "r"(a[3]), "r"(b[0]), "r"(b[1]));
}
__device__ __forceinline__ void ldmat4(unsigned* a, const __half* p) {
    unsigned addr = (unsigned)__cvta_generic_to_shared(p);
    asm volatile("ldmatrix.sync.aligned.m8n8.x4.shared.b16 {%0,%1,%2,%3}, [%4];"
                 : "=r"(a[0]), "=r"(a[1]), "=r"(a[2]), "=r"(a[3]) : "r"(addr));
}
__device__ __forceinline__ unsigned packh2(float a, float b) {
    __half2 t;
    t.x = __float2half_rn(a);
    t.y = __float2half_rn(b);
    return *reinterpret_cast<unsigned*>(&t);
}

// single-term fp16 GEMM: acc += A@W^T  (M=128, N=128, K=128)
// A: [m][k] smem stride KPAD; W: [n][k] smem stride KPAD.
// Warp computes 128 rows x 16 cols (cols warp*16..+15).
__device__ __forceinline__ void gemm_f16(
    const __half* __restrict__ sA, const __half* __restrict__ sW,
    int warp, int lane, float acc[8][2][4])
{
    const __half* Arow = sA + (lane & 15)*KPAD + (lane >> 4)*8;
    const __half* Wb = sW + (warp*16 + (lane >> 2))*KPAD + (lane & 3)*2;
    #pragma unroll
    for (int k0 = 0; k0 < 128; k0 += 16) {
        unsigned b0[2], b1[2];
        b0[0] = *(const unsigned*)&Wb[k0];
        b0[1] = *(const unsigned*)&Wb[k0 + 8];
        b1[0] = *(const unsigned*)&Wb[8*KPAD + k0];
        b1[1] = *(const unsigned*)&Wb[8*KPAD + k0 + 8];
        #pragma unroll
        for (int mt = 0; mt < 8; mt++) {
            unsigned a[4];
            ldmat4(a, Arow + mt*16*KPAD + k0);
            mma_f16(acc[mt][0], a, b0);
            mma_f16(acc[mt][1], a, b1);
        }
    }
}

// ---------------- fused: GEMM1 + relu + GEMM2 + message + scatter ------------
__global__ __launch_bounds__(256, 2)
void fused_kernel(const float* __restrict__ ea,  const float* __restrict__ b1g,
                  const float* __restrict__ b2g, const int* __restrict__ eidx,
                  const float* __restrict__ esh)
{
    extern __shared__ char smem_raw[];
    __half* sA = (__half*)(smem_raw + OFF_A);          // 128 x KPAD fp16
    __half* sW = (__half*)(smem_raw + OFF_REG);        // 128 x KPAD fp16
    float*  sEw = (float*)(smem_raw + OFF_REG);        // 128 x EWPAD f32 (union)

    const int tid  = threadIdx.x;
    const int warp = tid >> 5, lane = tid & 31;
    const int row0 = blockIdx.x * 128;

    // ---- load A tile (128x128 f32 -> fp16) ----
    #pragma unroll
    for (int t = 0; t < 16; t++) {
        int idx = tid + t * 256;           // 0..4095 float4s
        int r = idx >> 5, q = (idx & 31) << 2;
        float4 v = *(const float4*)&ea[(size_t)(row0 + r)*NF + q];
        uint2 u = make_uint2(packh2(v.x, v.y), packh2(v.z, v.w));
        *(uint2*)&sA[r*KPAD + q] = u;
    }
    // ---- stage W1T ----
    #pragma unroll
    for (int t = 0; t < 8; t++) {
        int idx = tid + t * 256;
        int n = idx >> 4, q = (idx & 15) << 3;
        *(float4*)&sW[n*KPAD + q] = *(const float4*)&g_w1t[n*NF + q];
    }
    __syncthreads();

    // ---- GEMM1: H = relu(A@W1 + b1) ----
    float acc[8][2][4];
    {
        int colb = warp*16 + (lane & 3)*2;
        #pragma unroll
        for (int nt = 0; nt < 2; nt++) {
            float bc0 = b1g[colb + nt*8], bc1 = b1g[colb + nt*8 + 1];
            #pragma unroll
            for (int mt = 0; mt < 8; mt++) {
                acc[mt][nt][0] = bc0; acc[mt][nt][1] = bc1;
                acc[mt][nt][2] = bc0; acc[mt][nt][3] = bc1;
            }
        }
    }
    gemm_f16(sA, sW, warp, lane, acc);
    __syncthreads();   // everyone done reading sA

    // ---- relu -> fp16 H back into sA ----
    {
        int c0 = warp*16 + (lane & 3)*2;
        int r0 = lane >> 2;
        #pragma unroll
        for (int mt = 0; mt < 8; mt++) {
            #pragma unroll
            for (int nt = 0; nt < 2; nt++) {
                int col = c0 + nt*8;
                #pragma unroll
                for (int half = 0; half < 2; half++) {
                    int row = mt*16 + r0 + half*8;
                    float h0 = fmaxf(acc[mt][nt][half*2 + 0], 0.f);
                    float h1 = fmaxf(acc[mt][nt][half*2 + 1], 0.f);
                    *(unsigned*)&sA[row*KPAD + col] = packh2(h0, h1);
                }
            }
        }
    }

    // ---- per-edge metadata (2 threads per row) ----
    const int r_e = tid >> 1, l = tid & 1;
    const int grow = row0 + r_e;
    const int b = grow / EE;
    const int e = grow - b*EE;
    const int src = eidx[e];
    const int dst = eidx[EE + e];
    const float4 sh = *(const float4*)&esh[(size_t)grow*4];
    float xg[CIN];
    {
        const float4* xgp = (const float4*)&g_xnew[((size_t)b*NN + src)*CIN];
        #pragma unroll
        for (int t4 = 0; t4 < 4; t4++) {
            float4 v = xgp[t4];
            xg[t4*4+0] = v.x; xg[t4*4+1] = v.y; xg[t4*4+2] = v.z; xg[t4*4+3] = v.w;
        }
    }
    float o0[8] = {0,0,0,0,0,0,0,0};
    float d1[4] = {0,0,0,0};

    // ---- GEMM2 in 3 N-chunks of 128, fused message contraction ----
    for (int ch = 0; ch < 3; ch++) {
        __syncthreads();   // prev sEw consumers done / H writes visible (ch==0)
        #pragma unroll
        for (int t = 0; t < 8; t++) {
            int idx = tid + t * 256;
            int n = idx >> 4, q = (idx & 15) << 3;
            *(float4*)&sW[n*KPAD + q] = *(const float4*)&g_w2t[(size_t)(ch*128 + n)*NF + q];
        }
        __syncthreads();

        {
            int colb = ch*128 + warp*16 + (lane & 3)*2;
            #pragma unroll
            for (int nt = 0; nt < 2; nt++) {
                float bc0 = b2g[colb + nt*8], bc1 = b2g[colb + nt*8 + 1];
                #pragma unroll
                for (int mt = 0; mt < 8; mt++) {
                    acc[mt][nt][0] = bc0; acc[mt][nt][1] = bc1;
                    acc[mt][nt][2] = bc0; acc[mt][nt][3] = bc1;
                }
            }
        }
        gemm_f16(sA, sW, warp, lane, acc);
        __syncthreads();   // done reading sW; region becomes sEw

        {
            int c0 = warp*16 + (lane & 3)*2;
            int r0 = lane >> 2;
            #pragma unroll
            for (int mt = 0; mt < 8; mt++) {
                #pragma unroll
                for (int nt = 0; nt < 2; nt++) {
                    int col = c0 + nt*8;
                    *(float2*)&sEw[(mt*16 + r0    )*EWPAD + col] =
                        make_float2(acc[mt][nt][0], acc[mt][nt][1]);
                    *(float2*)&sEw[(mt*16 + r0 + 8)*EWPAD + col] =
                        make_float2(acc[mt][nt][2], acc[mt][nt][3]);
                }
            }
        }
        __syncthreads();

        // message partial accumulation from this ew chunk
        const float* er = &sEw[r_e*EWPAD];
        if (ch == 0) {
            #pragma unroll
            for (int oi = 0; oi < 8; oi++) {
                int c = l*8 + oi;
                #pragma unroll
                for (int i = 0; i < 8; i++) o0[oi] += xg[i] * er[i*16 + c];
            }
        } else if (ch == 1) {
            #pragma unroll
            for (int oi = 0; oi < 8; oi++) {
                int c = l*8 + oi;
                #pragma unroll
                for (int i = 0; i < 8; i++) o0[oi] += xg[i+8] * er[i*16 + c];
            }
        } else {
            #pragma unroll
            for (int oi = 0; oi < 4; oi++) {
                int c = l*4 + oi;
                #pragma unroll
                for (int i = 0; i < 16; i++) d1[oi] += xg[i] * er[i*8 + c];
            }
        }
    }

    // ---- scatter ----
    float* aggp = &g_agg[((size_t)b*NN + dst)*OUTD];
    float s0 = ALPHA_C * sh.x;
    #pragma unroll
    for (int oi = 0; oi < 8; oi++)
        atomicAdd(&aggp[l*8 + oi], s0 * o0[oi]);
    #pragma unroll
    for (int oi = 0; oi < 4; oi++) {
        int cch = l*4 + oi;
        float v = ALPHA_C * d1[oi];
        atomicAdd(&aggp[16 + cch*3 + 0], v * sh.y);
        atomicAdd(&aggp[16 + cch*3 + 1], v * sh.z);
        atomicAdd(&aggp[16 + cch*3 + 2], v * sh.w);
    }
}

// ---------------- mean-by-count + BN stats (proven) --------------------------
__global__ void stats_kernel() {
    int row = blockIdx.x * blockDim.x + threadIdx.x;
    float v[OUTD];
    if (row < BB*NN) {
        int n = row % NN;
        float inv = 1.0f / fmaxf(g_cnt[n], 1.0f);
        float4* p = (float4*)&g_agg[row*OUTD];
        #pragma unroll
        for (int t = 0; t < 10; t++) {
            float4 a = p[t];
            a.x *= inv; a.y *= inv; a.z *= inv; a.w *= inv;
            p[t] = a;
            v[t*4+0] = a.x; v[t*4+1] = a.y; v[t*4+2] = a.z; v[t*4+3] = a.w;
        }
    } else {
        #pragma unroll
        for (int c = 0; c < OUTD; c++) v[c] = 0.f;
    }
    #pragma unroll
    for (int c = 0; c < OUTD; c++) {
        float s = v[c], q = v[c]*v[c];
        #pragma unroll
        for (int off = 16; off > 0; off >>= 1) {
            s += __shfl_down_sync(0xffffffffu, s, off);
            q += __shfl_down_sync(0xffffffffu, q, off);
        }
        if ((threadIdx.x & 31) == 0) {
            atomicAdd(&g_sum[c],   s);
            atomicAdd(&g_sumsq[c], q);
        }
    }
}

__global__ void norm_kernel(float* __restrict__ out,
                            const float* __restrict__ gamma,
                            const float* __restrict__ beta) {
    int i = blockIdx.x * blockDim.x + threadIdx.x;
    if (i >= BB*NN*OUTD) return;
    int c = i % OUTD;
    const float invM = 1.0f / M_TOT;
    float mu  = g_sum[c] * invM;
    float var = g_sumsq[c] * invM - mu*mu;
    out[i] = (g_agg[i] - mu) * rsqrtf(var + BN_EPS_C) * gamma[c] + beta[c];
}

// ---------------- launch ------------------------------------------------------
extern "C" void kernel_launch(void* const* d_in, const int* in_sizes, int n_in,
                              void* d_out, int out_size) {
    const float* x     = (const float*)d_in[0];
    const int*   eidx  = (const int*)  d_in[1];
    const float* ea    = (const float*)d_in[2];
    const float* esh   = (const float*)d_in[3];
    const float* wr    = (const float*)d_in[4];
    const float* wi    = (const float*)d_in[5];
    const float* w1    = (const float*)d_in[6];
    const float* b1    = (const float*)d_in[7];
    const float* w2    = (const float*)d_in[8];
    const float* b2    = (const float*)d_in[9];
    const float* gamma = (const float*)d_in[10];
    const float* beta  = (const float*)d_in[11];
    float* out = (float*)d_out;

    cudaFuncSetAttribute(fused_kernel,
                         cudaFuncAttributeMaxDynamicSharedMemorySize, SMEM_BYTES);

    zero_kernel <<<(BB*NN*OUTD + 255)/256, 256>>>();
    xnew_kernel <<<(NN*CIN + 255)/256, 256>>>(x, wr, wi);
    count_kernel<<<(EE + 255)/256, 256>>>(eidx);
    prep_kernel <<<(WN*NF + 255)/256, 256>>>(w1, w2);
    fused_kernel<<<MROWS/128, 256, SMEM_BYTES>>>(ea, b1, b2, eidx, esh);
    stats_kernel<<<(BB*NN + 255)/256, 256>>>();
    norm_kernel <<<(BB*NN*OUTD + 255)/256, 256>>>(out, gamma, beta);
}